// round 1
// baseline (speedup 1.0000x reference)
#include <cuda_runtime.h>
#include <math.h>

// Problem shape (fixed by the dataset)
#define BATCH 2
#define NHH   4
#define NHEAD 8        // BATCH*NHH
#define TT    1024
#define NDIM  8192
#define DD    256

// Scratch: RoPE'd Q, same layout as Q [B,nh,T,N]; row factor per (head,t)
__device__ float g_QR[(size_t)NHEAD * TT * NDIM];   // 256 MB static scratch
__device__ float g_rowfac[NHEAD * TT];

// ---------------------------------------------------------------------------
// Kernel 1: RoPE.  One thread per even/odd pair.
// freq[n] = theta^(-q/N)/(2pi), q = floor(n/2)*2, theta = 2^16
//        => 2^(-n2/256) / (2pi)  with n2 = n/2
// ---------------------------------------------------------------------------
__global__ __launch_bounds__(256) void rope_kernel(const float* __restrict__ Q) {
    size_t p = (size_t)blockIdx.x * blockDim.x + threadIdx.x;   // pair index
    int    n2  = (int)(p & (NDIM / 2 - 1));
    size_t row = p >> 12;                 // / (NDIM/2)
    int    t   = (int)(row & (TT - 1));

    const float TWO_PI_F = 6.283185307179586f;
    float freq = exp2f(-(float)n2 * (1.0f / 256.0f)) * (1.0f / TWO_PI_F);
    float ph   = fmodf((float)t * freq, 1.0f) * TWO_PI_F;
    float s, c;
    sincosf(ph, &s, &c);

    size_t idx = row * NDIM + 2 * (size_t)n2;
    float2 v = *reinterpret_cast<const float2*>(Q + idx);
    float2 o;
    o.x = v.x * c - v.y * s;   // even: v_e*c - v_o*s
    o.y = v.y * c + v.x * s;   // odd : v_o*c + v_e*s
    *reinterpret_cast<float2*>(g_QR + idx) = o;
}

// ---------------------------------------------------------------------------
// Kernel 2: trace gate factor = 0.5 + 0.5*sigmoid(mean_D(traces))
// One block (256 threads) per (head, t) row; D == 256.
// ---------------------------------------------------------------------------
__global__ __launch_bounds__(256) void gate_kernel(const float* __restrict__ traces) {
    int row = blockIdx.x;                                  // NHEAD*TT rows
    float v = traces[(size_t)row * DD + threadIdx.x];
    #pragma unroll
    for (int o = 16; o; o >>= 1) v += __shfl_down_sync(0xffffffffu, v, o);
    __shared__ float ws[8];
    if ((threadIdx.x & 31) == 0) ws[threadIdx.x >> 5] = v;
    __syncthreads();
    if (threadIdx.x == 0) {
        float s = 0.f;
        #pragma unroll
        for (int i = 0; i < 8; i++) s += ws[i];
        float m = s * (1.0f / 256.0f);
        float g = 1.0f / (1.0f + expf(-m));
        g_rowfac[row] = 0.5f + 0.5f * g;
    }
}

// ---------------------------------------------------------------------------
// Kernel 3: scores = tril(QR QR^T, -1) * (1 + stdp) * rowfac
// 128x128 tile per block, 8x8 microtile, KC=16.  Upper tiles -> zeros.
// Interleaved mapping: row = t0 + ty + 16*i, col = s0 + tx + 16*j
//   => B smem reads stride 17 across tx: conflict-free; A reads broadcast.
// ---------------------------------------------------------------------------
__global__ __launch_bounds__(256) void scores_kernel(const float* __restrict__ scale_p,
                                                     float* __restrict__ S) {
    const int js = blockIdx.x, jt = blockIdx.y, head = blockIdx.z;
    const int t0 = jt * 128, s0 = js * 128;
    float* Sh = S + (size_t)head * TT * TT;
    const int tid = threadIdx.x;

    if (js > jt) {   // fully above diagonal: zero fill (d_out is poisoned)
        for (int i = tid; i < 128 * 128; i += 256) {
            int r = i >> 7, c = i & 127;
            Sh[(size_t)(t0 + r) * TT + (s0 + c)] = 0.0f;
        }
        return;
    }

    __shared__ float As[128][17];
    __shared__ float Bs[128][17];
    const float* A  = g_QR + (size_t)head * TT * NDIM + (size_t)t0 * NDIM;
    const float* Bp = g_QR + (size_t)head * TT * NDIM + (size_t)s0 * NDIM;
    const int tx = tid & 15, ty = tid >> 4;

    float acc[8][8];
    #pragma unroll
    for (int i = 0; i < 8; i++)
        #pragma unroll
        for (int j = 0; j < 8; j++) acc[i][j] = 0.f;

    for (int k0 = 0; k0 < NDIM; k0 += 16) {
        #pragma unroll
        for (int r = 0; r < 8; r++) {          // 2048 floats each / 256 thr
            int i = tid + r * 256;
            int row = i >> 4, kk = i & 15;     // coalesced 64B per 16 lanes
            As[row][kk] = A[(size_t)row * NDIM + k0 + kk];
            Bs[row][kk] = Bp[(size_t)row * NDIM + k0 + kk];
        }
        __syncthreads();
        #pragma unroll
        for (int kk = 0; kk < 16; kk++) {
            float a[8], b[8];
            #pragma unroll
            for (int i = 0; i < 8; i++) a[i] = As[ty + 16 * i][kk];
            #pragma unroll
            for (int j = 0; j < 8; j++) b[j] = Bs[tx + 16 * j][kk];
            #pragma unroll
            for (int i = 0; i < 8; i++)
                #pragma unroll
                for (int j = 0; j < 8; j++) acc[i][j] += a[i] * b[j];
        }
        __syncthreads();
    }

    const float sc = scale_p[0];
    #pragma unroll
    for (int i = 0; i < 8; i++) {
        int t = t0 + ty + 16 * i;
        float rf = g_rowfac[head * TT + t];
        #pragma unroll
        for (int j = 0; j < 8; j++) {
            int s = s0 + tx + 16 * j;
            float v = 0.0f;
            if (s < t) {
                float dt = (float)(t - s);
                float f  = 1.0f + 0.01f * expf(-dt / 20.0f) * sc;  // ltp only for dt>0
                v = acc[i][j] * f * rf;
            }
            Sh[(size_t)t * TT + s] = v;
        }
    }
}

// ---------------------------------------------------------------------------
// Kernel 4: output = scores @ V   (scores strictly lower-tri -> K loop bounded)
// 64(t) x 64(d) tile, 4x4 microtile, KC=16.
// ---------------------------------------------------------------------------
__global__ __launch_bounds__(256) void out_kernel(const float* __restrict__ S,
                                                  const float* __restrict__ V,
                                                  float* __restrict__ O) {
    const int jd = blockIdx.x, jt = blockIdx.y, head = blockIdx.z;
    const int b  = head >> 2;              // head = b*nh + h
    const int t0 = jt * 64, d0 = jd * 64;
    const float* Sh = S + (size_t)head * TT * TT;
    const float* Vb = V + (size_t)b * TT * DD;
    const int tid = threadIdx.x, tx = tid & 15, ty = tid >> 4;

    __shared__ float Ss[64][17];
    __shared__ float Vs[16][64];

    float acc[4][4];
    #pragma unroll
    for (int i = 0; i < 4; i++)
        #pragma unroll
        for (int j = 0; j < 4; j++) acc[i][j] = 0.f;

    const int kend = t0 + 64;              // rows of S beyond t are zero
    for (int k0 = 0; k0 < kend; k0 += 16) {
        #pragma unroll
        for (int r = 0; r < 4; r++) {
            int i = tid + r * 256;
            int row = i >> 4, kk = i & 15;
            Ss[row][kk] = Sh[(size_t)(t0 + row) * TT + k0 + kk];
        }
        {
            int kk = tid >> 6, col = tid & 63;
            #pragma unroll
            for (int r = 0; r < 4; r++)
                Vs[kk + 4 * r][col] = Vb[(size_t)(k0 + kk + 4 * r) * DD + d0 + col];
        }
        __syncthreads();
        #pragma unroll
        for (int kk = 0; kk < 16; kk++) {
            float a[4], bb[4];
            #pragma unroll
            for (int i = 0; i < 4; i++) a[i]  = Ss[ty + 16 * i][kk];
            #pragma unroll
            for (int j = 0; j < 4; j++) bb[j] = Vs[kk][tx + 16 * j];
            #pragma unroll
            for (int i = 0; i < 4; i++)
                #pragma unroll
                for (int j = 0; j < 4; j++) acc[i][j] += a[i] * bb[j];
        }
        __syncthreads();
    }

    #pragma unroll
    for (int i = 0; i < 4; i++) {
        int t = t0 + ty + 16 * i;
        #pragma unroll
        for (int j = 0; j < 4; j++) {
            int d = d0 + tx + 16 * j;
            O[((size_t)head * TT + t) * DD + d] = acc[i][j];
        }
    }
}

// ---------------------------------------------------------------------------
extern "C" void kernel_launch(void* const* d_in, const int* in_sizes, int n_in,
                              void* d_out, int out_size) {
    const float* Q      = (const float*)d_in[0];  // [2,4,1024,8192]
    const float* V      = (const float*)d_in[1];  // [2,1,1024,256]
    const float* traces = (const float*)d_in[2];  // [2,4,1024,256]
    const float* scale  = (const float*)d_in[3];  // [1]

    float* out    = (float*)d_out;                        // [2,4,1024,256]
    float* scores = out + (size_t)NHEAD * TT * DD;        // [2,4,1024,1024]

    // 1) RoPE:   NHEAD*TT*NDIM/2 pairs
    rope_kernel<<<(NHEAD * TT * (NDIM / 2)) / 256, 256>>>(Q);
    // 2) trace gate
    gate_kernel<<<NHEAD * TT, 256>>>(traces);
    // 3) scores GEMM + fused epilogue
    dim3 gs(TT / 128, TT / 128, NHEAD);
    scores_kernel<<<gs, 256>>>(scale, scores);
    // 4) output GEMM
    dim3 go(DD / 64, TT / 64, NHEAD);
    out_kernel<<<go, 256>>>(scores, V, out);
}

// round 4
// speedup vs baseline: 2.5666x; 2.5666x over previous
#include <cuda_runtime.h>
#include <cuda_bf16.h>
#include <math.h>
#include <stdint.h>

// Problem shape (fixed by the dataset)
#define NHEAD 8        // B*nh = 2*4
#define TT    1024
#define NDIM  8192
#define DD    256

// Static scratch (no allocs allowed)
__device__ __nv_bfloat162 g_QH[(size_t)NHEAD * TT * (NDIM / 2)];  // 128 MB hi part
__device__ __nv_bfloat162 g_QL[(size_t)NHEAD * TT * (NDIM / 2)];  // 128 MB lo part
__device__ float g_rowfac[NHEAD * TT];

// ---------------------------------------------------------------------------
// PTX helpers (plain sm_80+-class instructions only: cp.async, ldmatrix, mma)
// ---------------------------------------------------------------------------
__device__ __forceinline__ uint32_t smem_u32(const void* p) {
    uint32_t a;
    asm("{ .reg .u64 t; cvta.to.shared.u64 t, %1; cvt.u32.u64 %0, t; }"
        : "=r"(a) : "l"(p));
    return a;
}
__device__ __forceinline__ void cp_async16(uint32_t dst, const void* src) {
    asm volatile("cp.async.cg.shared.global [%0], [%1], 16;" :: "r"(dst), "l"(src) : "memory");
}
#define CP_COMMIT() asm volatile("cp.async.commit_group;" ::: "memory")
#define CP_WAIT(n)  asm volatile("cp.async.wait_group %0;" :: "n"(n) : "memory")

__device__ __forceinline__ void ldsm_x4(uint32_t* r, uint32_t addr) {
    asm volatile("ldmatrix.sync.aligned.m8n8.x4.shared.b16 {%0,%1,%2,%3}, [%4];"
                 : "=r"(r[0]), "=r"(r[1]), "=r"(r[2]), "=r"(r[3]) : "r"(addr));
}
__device__ __forceinline__ void mma_bf16(float* c, const uint32_t* a,
                                         uint32_t b0, uint32_t b1) {
    asm volatile("mma.sync.aligned.m16n8k16.row.col.f32.bf16.bf16.f32 "
                 "{%0,%1,%2,%3}, {%4,%5,%6,%7}, {%8,%9}, {%0,%1,%2,%3};"
                 : "+f"(c[0]), "+f"(c[1]), "+f"(c[2]), "+f"(c[3])
                 : "r"(a[0]), "r"(a[1]), "r"(a[2]), "r"(a[3]), "r"(b0), "r"(b1));
}

// ---------------------------------------------------------------------------
// Kernel 1: RoPE + hi/lo bf16 split. One thread per even/odd pair.
// ---------------------------------------------------------------------------
__global__ __launch_bounds__(256) void rope_split_kernel(const float* __restrict__ Q) {
    size_t p = (size_t)blockIdx.x * blockDim.x + threadIdx.x;   // pair index
    int    n2  = (int)(p & (NDIM / 2 - 1));
    size_t row = p >> 12;
    int    t   = (int)(row & (TT - 1));

    const float TWO_PI_F = 6.283185307179586f;
    float freq = exp2f(-(float)n2 * (1.0f / 256.0f)) * (1.0f / TWO_PI_F);
    float ph   = fmodf((float)t * freq, 1.0f) * TWO_PI_F;
    float s, c;
    sincosf(ph, &s, &c);

    float2 v = *reinterpret_cast<const float2*>(Q + row * NDIM + 2 * (size_t)n2);
    float ox = v.x * c - v.y * s;
    float oy = v.y * c + v.x * s;

    __nv_bfloat16 hx = __float2bfloat16(ox);
    __nv_bfloat16 hy = __float2bfloat16(oy);
    float lx = ox - __bfloat162float(hx);
    float ly = oy - __bfloat162float(hy);
    g_QH[p] = __nv_bfloat162(hx, hy);
    g_QL[p] = __nv_bfloat162(__float2bfloat16(lx), __float2bfloat16(ly));
}

// ---------------------------------------------------------------------------
// Kernel 2: trace gate factor = 0.5 + 0.5*sigmoid(mean_D(traces))
// ---------------------------------------------------------------------------
__global__ __launch_bounds__(256) void gate_kernel(const float* __restrict__ traces) {
    int row = blockIdx.x;
    float v = traces[(size_t)row * DD + threadIdx.x];
    #pragma unroll
    for (int o = 16; o; o >>= 1) v += __shfl_down_sync(0xffffffffu, v, o);
    __shared__ float ws[8];
    if ((threadIdx.x & 31) == 0) ws[threadIdx.x >> 5] = v;
    __syncthreads();
    if (threadIdx.x == 0) {
        float s = 0.f;
        #pragma unroll
        for (int i = 0; i < 8; i++) s += ws[i];
        float m = s * (1.0f / 256.0f);
        g_rowfac[row] = 0.5f + 0.5f * (1.0f / (1.0f + expf(-m)));
    }
}

// ---------------------------------------------------------------------------
// Kernel 3: scores via mma.sync bf16, 3-way split in fp32 accumulators.
// CTA 128x128, 8 warps (warp tile 32x64), KC=64, 3-stage cp.async pipeline.
// SW128 swizzle: off = row*128 + ((c ^ (row&7))<<4), c = 16B chunk (0..7).
// ---------------------------------------------------------------------------
#define KC 64
#define TILE_BYTES (128 * 128)          // 128 rows x 128B (64 bf16)
#define STAGE_BYTES (4 * TILE_BYTES)    // AH, AL, BH, BL
#define NSTAGE 3
#define SMEM_TOTAL (NSTAGE * STAGE_BYTES)

__global__ __launch_bounds__(256, 1) void scores_mma_kernel(const float* __restrict__ scale_p,
                                                            float* __restrict__ S) {
    const int js = blockIdx.x, jt = blockIdx.y, head = blockIdx.z;
    const int t0 = jt * 128, s0 = js * 128;
    float* Sh = S + (size_t)head * TT * TT;
    const int tid = threadIdx.x, wid = tid >> 5, lane = tid & 31;

    if (js > jt) {   // strictly above diagonal: zero fill (out buffer is poisoned)
        for (int i = tid; i < 128 * 32; i += 256) {
            int r = i >> 5, c4 = (i & 31) << 2;
            *reinterpret_cast<float4*>(&Sh[(size_t)(t0 + r) * TT + s0 + c4]) =
                make_float4(0.f, 0.f, 0.f, 0.f);
        }
        return;
    }

    extern __shared__ char smem[];
    const uint32_t sbase = smem_u32(smem);

    // Global tile base pointers (bytes)
    const char* pAH = (const char*)g_QH + ((size_t)head * TT + t0) * NDIM * 2;
    const char* pAL = (const char*)g_QL + ((size_t)head * TT + t0) * NDIM * 2;
    const char* pBH = (const char*)g_QH + ((size_t)head * TT + s0) * NDIM * 2;
    const char* pBL = (const char*)g_QL + ((size_t)head * TT + s0) * NDIM * 2;
    const char* srcs[4] = { pAH, pAL, pBH, pBL };

    // Async copy: 4096 16B-chunks per stage / 256 threads = 16 each.
    auto load_stage = [&](int stage, int k0) {
        uint32_t sb = sbase + stage * STAGE_BYTES;
        size_t kb = (size_t)k0 * 2;
        #pragma unroll
        for (int rep = 0; rep < 16; rep++) {
            int idx = tid + rep * 256;
            int tile = idx >> 10, row = (idx >> 3) & 127, c = idx & 7;
            uint32_t dst = sb + tile * TILE_BYTES + row * 128 + ((c ^ (row & 7)) << 4);
            cp_async16(dst, srcs[tile] + (size_t)row * (NDIM * 2) + kb + c * 16);
        }
        CP_COMMIT();
    };

    load_stage(0, 0);
    load_stage(1, KC);

    // Warp layout: 4 (m) x 2 (n); warp tile 32 x 64.
    const int wm = wid >> 1, wn = wid & 1;
    const int m0 = wm * 32, n0 = wn * 64;
    const int rig  = (lane & 7) + ((lane >> 3) & 1) * 8;  // row-in-group for ldsm
    const int csel = lane >> 4;                           // chunk select (0/1)
    const int xr   = lane & 7;                            // row&7 for swizzle xor

    float acc[2][8][4];
    #pragma unroll
    for (int mt = 0; mt < 2; mt++)
        #pragma unroll
        for (int j = 0; j < 8; j++)
            #pragma unroll
            for (int q = 0; q < 4; q++) acc[mt][j][q] = 0.f;

    const int iters = NDIM / KC;  // 128
    for (int k = 0; k < iters; k++) {
        const int buf = k % NSTAGE;
        if (k + 2 < iters) { load_stage((k + 2) % NSTAGE, (k + 2) * KC); CP_WAIT(2); }
        else if (k + 1 < iters) { CP_WAIT(1); }
        else { CP_WAIT(0); }
        __syncthreads();

        const uint32_t sb = sbase + buf * STAGE_BYTES;
        const uint32_t aH = sb, aL = sb + TILE_BYTES;
        const uint32_t bH = sb + 2 * TILE_BYTES, bL = sb + 3 * TILE_BYTES;

        #pragma unroll
        for (int kk = 0; kk < 4; kk++) {
            const int c = 2 * kk + csel;
            const uint32_t swz = (uint32_t)((c ^ xr) << 4);

            uint32_t ah[2][4], al[2][4];
            #pragma unroll
            for (int mt = 0; mt < 2; mt++) {
                uint32_t roff = (uint32_t)(m0 + mt * 16 + rig) * 128 + swz;
                ldsm_x4(ah[mt], aH + roff);
                ldsm_x4(al[mt], aL + roff);
            }
            uint32_t bh[4][4], bl[4][4];
            #pragma unroll
            for (int nt = 0; nt < 4; nt++) {
                uint32_t roff = (uint32_t)(n0 + nt * 16 + rig) * 128 + swz;
                ldsm_x4(bh[nt], bH + roff);
                ldsm_x4(bl[nt], bL + roff);
            }
            #pragma unroll
            for (int mt = 0; mt < 2; mt++)
                #pragma unroll
                for (int nt = 0; nt < 4; nt++) {
                    // hi*hi
                    mma_bf16(acc[mt][2 * nt],     ah[mt], bh[nt][0], bh[nt][2]);
                    mma_bf16(acc[mt][2 * nt + 1], ah[mt], bh[nt][1], bh[nt][3]);
                    // hi*lo
                    mma_bf16(acc[mt][2 * nt],     ah[mt], bl[nt][0], bl[nt][2]);
                    mma_bf16(acc[mt][2 * nt + 1], ah[mt], bl[nt][1], bl[nt][3]);
                    // lo*hi
                    mma_bf16(acc[mt][2 * nt],     al[mt], bh[nt][0], bh[nt][2]);
                    mma_bf16(acc[mt][2 * nt + 1], al[mt], bh[nt][1], bh[nt][3]);
                }
        }
        __syncthreads();   // protect buffer before next-iter overwrite
    }

    // Epilogue: tril(-1) * (1 + 0.01*exp(-dt/20)*scale) * rowfac, float2 stores
    const float sc = scale_p[0];
    const int lq = lane >> 2, lr = lane & 3;
    #pragma unroll
    for (int mt = 0; mt < 2; mt++) {
        const int tr0 = t0 + m0 + mt * 16 + lq;
        const float rf0 = g_rowfac[head * TT + tr0];
        const float rf1 = g_rowfac[head * TT + tr0 + 8];
        #pragma unroll
        for (int j = 0; j < 8; j++) {
            const int scol = s0 + n0 + j * 8 + 2 * lr;
            float2 o0, o1;
            #pragma unroll
            for (int w = 0; w < 2; w++) {
                int s = scol + w;
                float v0 = 0.f, v1 = 0.f;
                if (s < tr0) {
                    float dt = (float)(tr0 - s);
                    v0 = acc[mt][j][w] * (1.0f + 0.01f * __expf(-dt * 0.05f) * sc) * rf0;
                }
                if (s < tr0 + 8) {
                    float dt = (float)(tr0 + 8 - s);
                    v1 = acc[mt][j][2 + w] * (1.0f + 0.01f * __expf(-dt * 0.05f) * sc) * rf1;
                }
                (&o0.x)[w] = v0;
                (&o1.x)[w] = v1;
            }
            *reinterpret_cast<float2*>(&Sh[(size_t)tr0 * TT + scol]) = o0;
            *reinterpret_cast<float2*>(&Sh[(size_t)(tr0 + 8) * TT + scol]) = o1;
        }
    }
}

// ---------------------------------------------------------------------------
// Kernel 4: output = scores @ V   (K loop bounded by strict lower-tri)
// ---------------------------------------------------------------------------
__global__ __launch_bounds__(256) void out_kernel(const float* __restrict__ S,
                                                  const float* __restrict__ V,
                                                  float* __restrict__ O) {
    const int jd = blockIdx.x, jt = blockIdx.y, head = blockIdx.z;
    const int b  = head >> 2;
    const int t0 = jt * 64, d0 = jd * 64;
    const float* Sh = S + (size_t)head * TT * TT;
    const float* Vb = V + (size_t)b * TT * DD;
    const int tid = threadIdx.x, tx = tid & 15, ty = tid >> 4;

    __shared__ float Ss[64][17];
    __shared__ float Vs[16][64];

    float acc[4][4];
    #pragma unroll
    for (int i = 0; i < 4; i++)
        #pragma unroll
        for (int j = 0; j < 4; j++) acc[i][j] = 0.f;

    const int kend = t0 + 64;
    for (int k0 = 0; k0 < kend; k0 += 16) {
        #pragma unroll
        for (int r = 0; r < 4; r++) {
            int i = tid + r * 256;
            int row = i >> 4, kk = i & 15;
            Ss[row][kk] = Sh[(size_t)(t0 + row) * TT + k0 + kk];
        }
        {
            int kk = tid >> 6, col = tid & 63;
            #pragma unroll
            for (int r = 0; r < 4; r++)
                Vs[kk + 4 * r][col] = Vb[(size_t)(k0 + kk + 4 * r) * DD + d0 + col];
        }
        __syncthreads();
        #pragma unroll
        for (int kk = 0; kk < 16; kk++) {
            float a[4], bb[4];
            #pragma unroll
            for (int i = 0; i < 4; i++) a[i]  = Ss[ty + 16 * i][kk];
            #pragma unroll
            for (int j = 0; j < 4; j++) bb[j] = Vs[kk][tx + 16 * j];
            #pragma unroll
            for (int i = 0; i < 4; i++)
                #pragma unroll
                for (int j = 0; j < 4; j++) acc[i][j] += a[i] * bb[j];
        }
        __syncthreads();
    }

    #pragma unroll
    for (int i = 0; i < 4; i++) {
        int t = t0 + ty + 16 * i;
        #pragma unroll
        for (int j = 0; j < 4; j++)
            O[((size_t)head * TT + t) * DD + d0 + tx + 16 * j] = acc[i][j];
    }
}

// ---------------------------------------------------------------------------
extern "C" void kernel_launch(void* const* d_in, const int* in_sizes, int n_in,
                              void* d_out, int out_size) {
    const float* Q      = (const float*)d_in[0];
    const float* V      = (const float*)d_in[1];
    const float* traces = (const float*)d_in[2];
    const float* scale  = (const float*)d_in[3];

    float* out    = (float*)d_out;
    float* scores = out + (size_t)NHEAD * TT * DD;

    cudaFuncSetAttribute(scores_mma_kernel,
                         cudaFuncAttributeMaxDynamicSharedMemorySize, SMEM_TOTAL);

    rope_split_kernel<<<(NHEAD * TT * (NDIM / 2)) / 256, 256>>>(Q);
    gate_kernel<<<NHEAD * TT, 256>>>(traces);
    dim3 gs(TT / 128, TT / 128, NHEAD);
    scores_mma_kernel<<<gs, 256, SMEM_TOTAL>>>(scale, scores);
    dim3 go(DD / 64, TT / 64, NHEAD);
    out_kernel<<<go, 256>>>(scores, V, out);
}

// round 5
// speedup vs baseline: 2.8120x; 1.0956x over previous
#include <cuda_runtime.h>
#include <cuda_bf16.h>
#include <math.h>
#include <stdint.h>

// Problem shape (fixed by the dataset)
#define NHEAD 8        // B*nh = 2*4
#define TT    1024
#define NDIM  8192
#define DD    256

// Static scratch (no allocs allowed)
__device__ __nv_bfloat162 g_QH[(size_t)NHEAD * TT * (NDIM / 2)];  // 128 MB hi part
__device__ __nv_bfloat162 g_QL[(size_t)NHEAD * TT * (NDIM / 2)];  // 128 MB lo part
__device__ __nv_bfloat16  g_SH[(size_t)NHEAD * TT * TT];          // scores hi (16 MB)
__device__ __nv_bfloat16  g_SL[(size_t)NHEAD * TT * TT];          // scores lo (16 MB)
__device__ __nv_bfloat16  g_VtH[(size_t)2 * DD * TT];             // V^T hi [b][d][s]
__device__ __nv_bfloat16  g_VtL[(size_t)2 * DD * TT];             // V^T lo
__device__ float g_rowfac[NHEAD * TT];

// ---------------------------------------------------------------------------
// PTX helpers (plain sm_80+-class instructions only: cp.async, ldmatrix, mma)
// ---------------------------------------------------------------------------
__device__ __forceinline__ uint32_t smem_u32(const void* p) {
    uint32_t a;
    asm("{ .reg .u64 t; cvta.to.shared.u64 t, %1; cvt.u32.u64 %0, t; }"
        : "=r"(a) : "l"(p));
    return a;
}
__device__ __forceinline__ void cp_async16(uint32_t dst, const void* src) {
    asm volatile("cp.async.cg.shared.global [%0], [%1], 16;" :: "r"(dst), "l"(src) : "memory");
}
#define CP_COMMIT() asm volatile("cp.async.commit_group;" ::: "memory")
#define CP_WAIT(n)  asm volatile("cp.async.wait_group %0;" :: "n"(n) : "memory")

__device__ __forceinline__ void ldsm_x4(uint32_t* r, uint32_t addr) {
    asm volatile("ldmatrix.sync.aligned.m8n8.x4.shared.b16 {%0,%1,%2,%3}, [%4];"
                 : "=r"(r[0]), "=r"(r[1]), "=r"(r[2]), "=r"(r[3]) : "r"(addr));
}
__device__ __forceinline__ void mma_bf16(float* c, const uint32_t* a,
                                         uint32_t b0, uint32_t b1) {
    asm volatile("mma.sync.aligned.m16n8k16.row.col.f32.bf16.bf16.f32 "
                 "{%0,%1,%2,%3}, {%4,%5,%6,%7}, {%8,%9}, {%0,%1,%2,%3};"
                 : "+f"(c[0]), "+f"(c[1]), "+f"(c[2]), "+f"(c[3])
                 : "r"(a[0]), "r"(a[1]), "r"(a[2]), "r"(a[3]), "r"(b0), "r"(b1));
}

#define KC 64
#define TILE_BYTES (128 * 128)          // 128 rows x 128B (64 bf16)
#define STAGE_BYTES (4 * TILE_BYTES)    // 4 operand tiles per stage
#define NSTAGE 3
#define SMEM_TOTAL (NSTAGE * STAGE_BYTES)

// ---------------------------------------------------------------------------
// Kernel 1: RoPE + hi/lo bf16 split. One thread per even/odd pair.
// ---------------------------------------------------------------------------
__global__ __launch_bounds__(256) void rope_split_kernel(const float* __restrict__ Q) {
    size_t p = (size_t)blockIdx.x * blockDim.x + threadIdx.x;   // pair index
    int    n2  = (int)(p & (NDIM / 2 - 1));
    size_t row = p >> 12;
    int    t   = (int)(row & (TT - 1));

    const float TWO_PI_F = 6.283185307179586f;
    float freq = exp2f(-(float)n2 * (1.0f / 256.0f)) * (1.0f / TWO_PI_F);
    float ph   = fmodf((float)t * freq, 1.0f) * TWO_PI_F;
    float s, c;
    sincosf(ph, &s, &c);

    float2 v = *reinterpret_cast<const float2*>(Q + row * NDIM + 2 * (size_t)n2);
    float ox = v.x * c - v.y * s;
    float oy = v.y * c + v.x * s;

    __nv_bfloat16 hx = __float2bfloat16(ox);
    __nv_bfloat16 hy = __float2bfloat16(oy);
    float lx = ox - __bfloat162float(hx);
    float ly = oy - __bfloat162float(hy);
    g_QH[p] = __nv_bfloat162(hx, hy);
    g_QL[p] = __nv_bfloat162(__float2bfloat16(lx), __float2bfloat16(ly));
}

// ---------------------------------------------------------------------------
// Kernel 2: trace gate factor = 0.5 + 0.5*sigmoid(mean_D(traces))
// ---------------------------------------------------------------------------
__global__ __launch_bounds__(256) void gate_kernel(const float* __restrict__ traces) {
    int row = blockIdx.x;
    float v = traces[(size_t)row * DD + threadIdx.x];
    #pragma unroll
    for (int o = 16; o; o >>= 1) v += __shfl_down_sync(0xffffffffu, v, o);
    __shared__ float ws[8];
    if ((threadIdx.x & 31) == 0) ws[threadIdx.x >> 5] = v;
    __syncthreads();
    if (threadIdx.x == 0) {
        float s = 0.f;
        #pragma unroll
        for (int i = 0; i < 8; i++) s += ws[i];
        float m = s * (1.0f / 256.0f);
        g_rowfac[row] = 0.5f + 0.5f * (1.0f / (1.0f + expf(-m)));
    }
}

// ---------------------------------------------------------------------------
// Kernel 2b: V transpose + hi/lo split:  Vt[b][d][s] = V[b][s][d]
// grid (DD/32, TT/32, 2), block (32, 8)
// ---------------------------------------------------------------------------
__global__ __launch_bounds__(256) void vsplit_kernel(const float* __restrict__ V) {
    const int b = blockIdx.z, d0 = blockIdx.x * 32, s0 = blockIdx.y * 32;
    __shared__ float tile[32][33];
    const int tx = threadIdx.x, ty = threadIdx.y;
    #pragma unroll
    for (int i = 0; i < 4; i++) {
        int s = s0 + ty + 8 * i;
        tile[ty + 8 * i][tx] = V[((size_t)b * TT + s) * DD + d0 + tx];
    }
    __syncthreads();
    #pragma unroll
    for (int i = 0; i < 4; i++) {
        int d = d0 + ty + 8 * i;
        float v = tile[tx][ty + 8 * i];
        __nv_bfloat16 h = __float2bfloat16(v);
        size_t idx = ((size_t)b * DD + d) * TT + s0 + tx;
        g_VtH[idx] = h;
        g_VtL[idx] = __float2bfloat16(v - __bfloat162float(h));
    }
}

// ---------------------------------------------------------------------------
// Kernel 3: scores via mma.sync bf16, 3-way split in fp32 accumulators.
// CTA 128x128, 8 warps (warp tile 32x64), KC=64, 3-stage cp.async pipeline.
// SW128 swizzle: off = row*128 + ((c ^ (row&7))<<4), c = 16B chunk (0..7).
// Epilogue also emits bf16 hi/lo of scores into g_SH/g_SL for the out GEMM.
// ---------------------------------------------------------------------------
__global__ __launch_bounds__(256, 1) void scores_mma_kernel(const float* __restrict__ scale_p,
                                                            float* __restrict__ S) {
    const int js = blockIdx.x, jt = blockIdx.y, head = blockIdx.z;
    const int t0 = jt * 128, s0 = js * 128;
    float* Sh = S + (size_t)head * TT * TT;
    const int tid = threadIdx.x, wid = tid >> 5, lane = tid & 31;

    if (js > jt) {   // strictly above diagonal: zero fill fp32 output only
        for (int i = tid; i < 128 * 32; i += 256) {
            int r = i >> 5, c4 = (i & 31) << 2;
            *reinterpret_cast<float4*>(&Sh[(size_t)(t0 + r) * TT + s0 + c4]) =
                make_float4(0.f, 0.f, 0.f, 0.f);
        }
        return;
    }

    extern __shared__ char smem[];
    const uint32_t sbase = smem_u32(smem);

    const char* pAH = (const char*)g_QH + ((size_t)head * TT + t0) * NDIM * 2;
    const char* pAL = (const char*)g_QL + ((size_t)head * TT + t0) * NDIM * 2;
    const char* pBH = (const char*)g_QH + ((size_t)head * TT + s0) * NDIM * 2;
    const char* pBL = (const char*)g_QL + ((size_t)head * TT + s0) * NDIM * 2;
    const char* srcs[4] = { pAH, pAL, pBH, pBL };

    auto load_stage = [&](int stage, int k0) {
        uint32_t sb = sbase + stage * STAGE_BYTES;
        size_t kb = (size_t)k0 * 2;
        #pragma unroll
        for (int rep = 0; rep < 16; rep++) {
            int idx = tid + rep * 256;
            int tile = idx >> 10, row = (idx >> 3) & 127, c = idx & 7;
            uint32_t dst = sb + tile * TILE_BYTES + row * 128 + ((c ^ (row & 7)) << 4);
            cp_async16(dst, srcs[tile] + (size_t)row * (NDIM * 2) + kb + c * 16);
        }
        CP_COMMIT();
    };

    load_stage(0, 0);
    load_stage(1, KC);

    const int wm = wid >> 1, wn = wid & 1;
    const int m0 = wm * 32, n0 = wn * 64;
    const int rig  = (lane & 7) + ((lane >> 3) & 1) * 8;
    const int csel = lane >> 4;
    const int xr   = lane & 7;

    float acc[2][8][4];
    #pragma unroll
    for (int mt = 0; mt < 2; mt++)
        #pragma unroll
        for (int j = 0; j < 8; j++)
            #pragma unroll
            for (int q = 0; q < 4; q++) acc[mt][j][q] = 0.f;

    const int iters = NDIM / KC;  // 128
    for (int k = 0; k < iters; k++) {
        const int buf = k % NSTAGE;
        if (k + 1 < iters) { CP_WAIT(1); } else { CP_WAIT(0); }
        __syncthreads();                       // single barrier per iter
        if (k + 2 < iters) load_stage((k + 2) % NSTAGE, (k + 2) * KC);

        const uint32_t sb = sbase + buf * STAGE_BYTES;
        const uint32_t aH = sb, aL = sb + TILE_BYTES;
        const uint32_t bH = sb + 2 * TILE_BYTES, bL = sb + 3 * TILE_BYTES;

        #pragma unroll
        for (int kk = 0; kk < 4; kk++) {
            const int c = 2 * kk + csel;
            const uint32_t swz = (uint32_t)((c ^ xr) << 4);

            uint32_t ah[2][4], al[2][4];
            #pragma unroll
            for (int mt = 0; mt < 2; mt++) {
                uint32_t roff = (uint32_t)(m0 + mt * 16 + rig) * 128 + swz;
                ldsm_x4(ah[mt], aH + roff);
                ldsm_x4(al[mt], aL + roff);
            }
            uint32_t bh[4][4], bl[4][4];
            #pragma unroll
            for (int nt = 0; nt < 4; nt++) {
                uint32_t roff = (uint32_t)(n0 + nt * 16 + rig) * 128 + swz;
                ldsm_x4(bh[nt], bH + roff);
                ldsm_x4(bl[nt], bL + roff);
            }
            #pragma unroll
            for (int mt = 0; mt < 2; mt++)
                #pragma unroll
                for (int nt = 0; nt < 4; nt++) {
                    mma_bf16(acc[mt][2 * nt],     ah[mt], bh[nt][0], bh[nt][2]);
                    mma_bf16(acc[mt][2 * nt + 1], ah[mt], bh[nt][1], bh[nt][3]);
                    mma_bf16(acc[mt][2 * nt],     ah[mt], bl[nt][0], bl[nt][2]);
                    mma_bf16(acc[mt][2 * nt + 1], ah[mt], bl[nt][1], bl[nt][3]);
                    mma_bf16(acc[mt][2 * nt],     al[mt], bh[nt][0], bh[nt][2]);
                    mma_bf16(acc[mt][2 * nt + 1], al[mt], bh[nt][1], bh[nt][3]);
                }
        }
    }

    // Epilogue: tril(-1) * (1 + 0.01*exp(-dt/20)*scale) * rowfac
    // Writes fp32 scores to d_out AND bf16 hi/lo to g_SH/g_SL.
    const float sc = scale_p[0];
    const int lq = lane >> 2, lr = lane & 3;
    __nv_bfloat16* SHh = g_SH + (size_t)head * TT * TT;
    __nv_bfloat16* SLh = g_SL + (size_t)head * TT * TT;
    #pragma unroll
    for (int mt = 0; mt < 2; mt++) {
        const int tr0 = t0 + m0 + mt * 16 + lq;
        const float rf0 = g_rowfac[head * TT + tr0];
        const float rf1 = g_rowfac[head * TT + tr0 + 8];
        #pragma unroll
        for (int j = 0; j < 8; j++) {
            const int scol = s0 + n0 + j * 8 + 2 * lr;
            float2 o0, o1;
            #pragma unroll
            for (int w = 0; w < 2; w++) {
                int s = scol + w;
                float v0 = 0.f, v1 = 0.f;
                if (s < tr0) {
                    float dt = (float)(tr0 - s);
                    v0 = acc[mt][j][w] * (1.0f + 0.01f * __expf(-dt * 0.05f) * sc) * rf0;
                }
                if (s < tr0 + 8) {
                    float dt = (float)(tr0 + 8 - s);
                    v1 = acc[mt][j][2 + w] * (1.0f + 0.01f * __expf(-dt * 0.05f) * sc) * rf1;
                }
                (&o0.x)[w] = v0;
                (&o1.x)[w] = v1;
            }
            *reinterpret_cast<float2*>(&Sh[(size_t)tr0 * TT + scol]) = o0;
            *reinterpret_cast<float2*>(&Sh[(size_t)(tr0 + 8) * TT + scol]) = o1;

            __nv_bfloat16 h0x = __float2bfloat16(o0.x), h0y = __float2bfloat16(o0.y);
            __nv_bfloat16 h1x = __float2bfloat16(o1.x), h1y = __float2bfloat16(o1.y);
            *reinterpret_cast<__nv_bfloat162*>(&SHh[(size_t)tr0 * TT + scol]) =
                __nv_bfloat162(h0x, h0y);
            *reinterpret_cast<__nv_bfloat162*>(&SHh[(size_t)(tr0 + 8) * TT + scol]) =
                __nv_bfloat162(h1x, h1y);
            *reinterpret_cast<__nv_bfloat162*>(&SLh[(size_t)tr0 * TT + scol]) =
                __nv_bfloat162(__float2bfloat16(o0.x - __bfloat162float(h0x)),
                               __float2bfloat16(o0.y - __bfloat162float(h0y)));
            *reinterpret_cast<__nv_bfloat162*>(&SLh[(size_t)(tr0 + 8) * TT + scol]) =
                __nv_bfloat162(__float2bfloat16(o1.x - __bfloat162float(h1x)),
                               __float2bfloat16(o1.y - __bfloat162float(h1y)));
        }
    }
}

// ---------------------------------------------------------------------------
// Kernel 4: output = scores @ V via bf16 split MMA.
// CTA tile 128(t) x 128(d); A = SH/SL (K-major over s), B = VtH/VtL (K-major).
// K loop bounded at t0+128 (strict lower-tri scores).
// ---------------------------------------------------------------------------
__global__ __launch_bounds__(256, 1) void out_mma_kernel(float* __restrict__ O) {
    const int jd = blockIdx.x, jt = blockIdx.y, head = blockIdx.z;
    const int b  = head >> 2;
    const int t0 = jt * 128, d0 = jd * 128;
    const int tid = threadIdx.x, wid = tid >> 5, lane = tid & 31;

    extern __shared__ char smem[];
    const uint32_t sbase = smem_u32(smem);

    const char* pAH = (const char*)(g_SH  + (size_t)head * TT * TT + (size_t)t0 * TT);
    const char* pAL = (const char*)(g_SL  + (size_t)head * TT * TT + (size_t)t0 * TT);
    const char* pBH = (const char*)(g_VtH + ((size_t)b * DD + d0) * TT);
    const char* pBL = (const char*)(g_VtL + ((size_t)b * DD + d0) * TT);
    const char* srcs[4] = { pAH, pAL, pBH, pBL };

    auto load_stage = [&](int stage, int k0) {
        uint32_t sb = sbase + stage * STAGE_BYTES;
        size_t kb = (size_t)k0 * 2;
        #pragma unroll
        for (int rep = 0; rep < 16; rep++) {
            int idx = tid + rep * 256;
            int tile = idx >> 10, row = (idx >> 3) & 127, c = idx & 7;
            uint32_t dst = sb + tile * TILE_BYTES + row * 128 + ((c ^ (row & 7)) << 4);
            cp_async16(dst, srcs[tile] + (size_t)row * (TT * 2) + kb + c * 16);
        }
        CP_COMMIT();
    };

    const int iters = 2 * (jt + 1);     // (t0+128)/KC
    load_stage(0, 0);
    if (iters > 1) load_stage(1, KC);

    const int wm = wid >> 1, wn = wid & 1;
    const int m0 = wm * 32, n0 = wn * 64;
    const int rig  = (lane & 7) + ((lane >> 3) & 1) * 8;
    const int csel = lane >> 4;
    const int xr   = lane & 7;

    float acc[2][8][4];
    #pragma unroll
    for (int mt = 0; mt < 2; mt++)
        #pragma unroll
        for (int j = 0; j < 8; j++)
            #pragma unroll
            for (int q = 0; q < 4; q++) acc[mt][j][q] = 0.f;

    for (int k = 0; k < iters; k++) {
        const int buf = k % NSTAGE;
        if (k + 1 < iters) { CP_WAIT(1); } else { CP_WAIT(0); }
        __syncthreads();
        if (k + 2 < iters) load_stage((k + 2) % NSTAGE, (k + 2) * KC);

        const uint32_t sb = sbase + buf * STAGE_BYTES;
        const uint32_t aH = sb, aL = sb + TILE_BYTES;
        const uint32_t bH = sb + 2 * TILE_BYTES, bL = sb + 3 * TILE_BYTES;

        #pragma unroll
        for (int kk = 0; kk < 4; kk++) {
            const int c = 2 * kk + csel;
            const uint32_t swz = (uint32_t)((c ^ xr) << 4);

            uint32_t ah[2][4], al[2][4];
            #pragma unroll
            for (int mt = 0; mt < 2; mt++) {
                uint32_t roff = (uint32_t)(m0 + mt * 16 + rig) * 128 + swz;
                ldsm_x4(ah[mt], aH + roff);
                ldsm_x4(al[mt], aL + roff);
            }
            uint32_t bh[4][4], bl[4][4];
            #pragma unroll
            for (int nt = 0; nt < 4; nt++) {
                uint32_t roff = (uint32_t)(n0 + nt * 16 + rig) * 128 + swz;
                ldsm_x4(bh[nt], bH + roff);
                ldsm_x4(bl[nt], bL + roff);
            }
            #pragma unroll
            for (int mt = 0; mt < 2; mt++)
                #pragma unroll
                for (int nt = 0; nt < 4; nt++) {
                    mma_bf16(acc[mt][2 * nt],     ah[mt], bh[nt][0], bh[nt][2]);
                    mma_bf16(acc[mt][2 * nt + 1], ah[mt], bh[nt][1], bh[nt][3]);
                    mma_bf16(acc[mt][2 * nt],     ah[mt], bl[nt][0], bl[nt][2]);
                    mma_bf16(acc[mt][2 * nt + 1], ah[mt], bl[nt][1], bl[nt][3]);
                    mma_bf16(acc[mt][2 * nt],     al[mt], bh[nt][0], bh[nt][2]);
                    mma_bf16(acc[mt][2 * nt + 1], al[mt], bh[nt][1], bh[nt][3]);
                }
        }
    }

    // Epilogue: plain stores to O[head][t][d]
    const int lq = lane >> 2, lr = lane & 3;
    #pragma unroll
    for (int mt = 0; mt < 2; mt++) {
        const int tr0 = t0 + m0 + mt * 16 + lq;
        #pragma unroll
        for (int j = 0; j < 8; j++) {
            const int dcol = d0 + n0 + j * 8 + 2 * lr;
            float2 o0, o1;
            o0.x = acc[mt][j][0]; o0.y = acc[mt][j][1];
            o1.x = acc[mt][j][2]; o1.y = acc[mt][j][3];
            *reinterpret_cast<float2*>(&O[((size_t)head * TT + tr0) * DD + dcol]) = o0;
            *reinterpret_cast<float2*>(&O[((size_t)head * TT + tr0 + 8) * DD + dcol]) = o1;
        }
    }
}

// ---------------------------------------------------------------------------
extern "C" void kernel_launch(void* const* d_in, const int* in_sizes, int n_in,
                              void* d_out, int out_size) {
    const float* Q      = (const float*)d_in[0];
    const float* V      = (const float*)d_in[1];
    const float* traces = (const float*)d_in[2];
    const float* scale  = (const float*)d_in[3];

    float* out    = (float*)d_out;
    float* scores = out + (size_t)NHEAD * TT * DD;

    cudaFuncSetAttribute(scores_mma_kernel,
                         cudaFuncAttributeMaxDynamicSharedMemorySize, SMEM_TOTAL);
    cudaFuncSetAttribute(out_mma_kernel,
                         cudaFuncAttributeMaxDynamicSharedMemorySize, SMEM_TOTAL);

    rope_split_kernel<<<(NHEAD * TT * (NDIM / 2)) / 256, 256>>>(Q);
    gate_kernel<<<NHEAD * TT, 256>>>(traces);
    dim3 gv(DD / 32, TT / 32, 2);
    vsplit_kernel<<<gv, dim3(32, 8)>>>(V);
    dim3 gs(TT / 128, TT / 128, NHEAD);
    scores_mma_kernel<<<gs, 256, SMEM_TOTAL>>>(scale, scores);
    dim3 go(DD / 128, TT / 128, NHEAD);
    out_mma_kernel<<<go, 256, SMEM_TOTAL>>>(out);
}

// round 6
// speedup vs baseline: 2.9080x; 1.0341x over previous
#include <cuda_runtime.h>
#include <cuda_bf16.h>
#include <math.h>
#include <stdint.h>

// Problem shape (fixed by the dataset)
#define NHEAD 8        // B*nh = 2*4
#define TT    1024
#define NDIM  8192
#define DD    256

// Static scratch (no allocs allowed)
__device__ __nv_bfloat162 g_QH[(size_t)NHEAD * TT * (NDIM / 2)];  // 128 MB hi part
__device__ __nv_bfloat162 g_QL[(size_t)NHEAD * TT * (NDIM / 2)];  // 128 MB lo part
__device__ __nv_bfloat16  g_SH[(size_t)NHEAD * TT * TT];          // scores hi (16 MB)
__device__ __nv_bfloat16  g_SL[(size_t)NHEAD * TT * TT];          // scores lo (16 MB)
__device__ __nv_bfloat16  g_VtH[(size_t)2 * DD * TT];             // V^T hi [b][d][s]
__device__ __nv_bfloat16  g_VtL[(size_t)2 * DD * TT];             // V^T lo
__device__ float g_rowfac[NHEAD * TT];

// ---------------------------------------------------------------------------
// PTX helpers (plain sm_80+-class instructions only: cp.async, ldmatrix, mma)
// ---------------------------------------------------------------------------
__device__ __forceinline__ uint32_t smem_u32(const void* p) {
    uint32_t a;
    asm("{ .reg .u64 t; cvta.to.shared.u64 t, %1; cvt.u32.u64 %0, t; }"
        : "=r"(a) : "l"(p));
    return a;
}
__device__ __forceinline__ void cp_async16(uint32_t dst, const void* src) {
    asm volatile("cp.async.cg.shared.global [%0], [%1], 16;" :: "r"(dst), "l"(src) : "memory");
}
#define CP_COMMIT() asm volatile("cp.async.commit_group;" ::: "memory")
#define CP_WAIT(n)  asm volatile("cp.async.wait_group %0;" :: "n"(n) : "memory")

__device__ __forceinline__ void ldsm_x4(uint32_t* r, uint32_t addr) {
    asm volatile("ldmatrix.sync.aligned.m8n8.x4.shared.b16 {%0,%1,%2,%3}, [%4];"
                 : "=r"(r[0]), "=r"(r[1]), "=r"(r[2]), "=r"(r[3]) : "r"(addr));
}
__device__ __forceinline__ void mma_bf16(float* c, const uint32_t* a,
                                         uint32_t b0, uint32_t b1) {
    asm volatile("mma.sync.aligned.m16n8k16.row.col.f32.bf16.bf16.f32 "
                 "{%0,%1,%2,%3}, {%4,%5,%6,%7}, {%8,%9}, {%0,%1,%2,%3};"
                 : "+f"(c[0]), "+f"(c[1]), "+f"(c[2]), "+f"(c[3])
                 : "r"(a[0]), "r"(a[1]), "r"(a[2]), "r"(a[3]), "r"(b0), "r"(b1));
}

#define KC 64
#define TILE_BYTES (128 * 128)          // 128 rows x 128B (64 bf16)
#define STAGE_BYTES (4 * TILE_BYTES)    // 4 operand tiles per stage
#define NSTAGE 3
#define SMEM_TOTAL (NSTAGE * STAGE_BYTES)

// ---------------------------------------------------------------------------
// Kernel 1: RoPE + hi/lo bf16 split. One thread per even/odd pair.
// ---------------------------------------------------------------------------
__global__ __launch_bounds__(256) void rope_split_kernel(const float* __restrict__ Q) {
    size_t p = (size_t)blockIdx.x * blockDim.x + threadIdx.x;   // pair index
    int    n2  = (int)(p & (NDIM / 2 - 1));
    size_t row = p >> 12;
    int    t   = (int)(row & (TT - 1));

    const float TWO_PI_F = 6.283185307179586f;
    float freq = exp2f(-(float)n2 * (1.0f / 256.0f)) * (1.0f / TWO_PI_F);
    float ph   = fmodf((float)t * freq, 1.0f) * TWO_PI_F;
    float s, c;
    sincosf(ph, &s, &c);

    float2 v = *reinterpret_cast<const float2*>(Q + row * NDIM + 2 * (size_t)n2);
    float ox = v.x * c - v.y * s;
    float oy = v.y * c + v.x * s;

    __nv_bfloat16 hx = __float2bfloat16(ox);
    __nv_bfloat16 hy = __float2bfloat16(oy);
    float lx = ox - __bfloat162float(hx);
    float ly = oy - __bfloat162float(hy);
    g_QH[p] = __nv_bfloat162(hx, hy);
    g_QL[p] = __nv_bfloat162(__float2bfloat16(lx), __float2bfloat16(ly));
}

// ---------------------------------------------------------------------------
// Kernel 2: trace gate factor = 0.5 + 0.5*sigmoid(mean_D(traces))
// ---------------------------------------------------------------------------
__global__ __launch_bounds__(256) void gate_kernel(const float* __restrict__ traces) {
    int row = blockIdx.x;
    float v = traces[(size_t)row * DD + threadIdx.x];
    #pragma unroll
    for (int o = 16; o; o >>= 1) v += __shfl_down_sync(0xffffffffu, v, o);
    __shared__ float ws[8];
    if ((threadIdx.x & 31) == 0) ws[threadIdx.x >> 5] = v;
    __syncthreads();
    if (threadIdx.x == 0) {
        float s = 0.f;
        #pragma unroll
        for (int i = 0; i < 8; i++) s += ws[i];
        float m = s * (1.0f / 256.0f);
        g_rowfac[row] = 0.5f + 0.5f * (1.0f / (1.0f + expf(-m)));
    }
}

// ---------------------------------------------------------------------------
// Kernel 2b: V transpose + hi/lo split:  Vt[b][d][s] = V[b][s][d]
// grid (DD/32, TT/32, 2), block (32, 8)
// ---------------------------------------------------------------------------
__global__ __launch_bounds__(256) void vsplit_kernel(const float* __restrict__ V) {
    const int b = blockIdx.z, d0 = blockIdx.x * 32, s0 = blockIdx.y * 32;
    __shared__ float tile[32][33];
    const int tx = threadIdx.x, ty = threadIdx.y;
    #pragma unroll
    for (int i = 0; i < 4; i++) {
        int s = s0 + ty + 8 * i;
        tile[ty + 8 * i][tx] = V[((size_t)b * TT + s) * DD + d0 + tx];
    }
    __syncthreads();
    #pragma unroll
    for (int i = 0; i < 4; i++) {
        int d = d0 + ty + 8 * i;
        float v = tile[tx][ty + 8 * i];
        __nv_bfloat16 h = __float2bfloat16(v);
        size_t idx = ((size_t)b * DD + d) * TT + s0 + tx;
        g_VtH[idx] = h;
        g_VtL[idx] = __float2bfloat16(v - __bfloat162float(h));
    }
}

// ---------------------------------------------------------------------------
// Kernel 3: scores via mma.sync bf16, 3-way split in fp32 accumulators.
// CTA 128x128, 8 warps (warp tile 32x64), KC=64, 3-stage cp.async pipeline.
// MMAs issued in 3 passes (hi*hi, hi*lo, lo*hi) so no accumulator is revisited
// within 16 MMA issues -> HMMA RAW latency fully hidden.
// ---------------------------------------------------------------------------
__global__ __launch_bounds__(256, 1) void scores_mma_kernel(const float* __restrict__ scale_p,
                                                            float* __restrict__ S) {
    const int js = blockIdx.x, jt = blockIdx.y, head = blockIdx.z;
    const int t0 = jt * 128, s0 = js * 128;
    float* Sh = S + (size_t)head * TT * TT;
    const int tid = threadIdx.x, wid = tid >> 5, lane = tid & 31;

    if (js > jt) {   // strictly above diagonal: zero fill fp32 output only
        for (int i = tid; i < 128 * 32; i += 256) {
            int r = i >> 5, c4 = (i & 31) << 2;
            *reinterpret_cast<float4*>(&Sh[(size_t)(t0 + r) * TT + s0 + c4]) =
                make_float4(0.f, 0.f, 0.f, 0.f);
        }
        return;
    }

    extern __shared__ char smem[];
    const uint32_t sbase = smem_u32(smem);

    const char* pAH = (const char*)g_QH + ((size_t)head * TT + t0) * NDIM * 2;
    const char* pAL = (const char*)g_QL + ((size_t)head * TT + t0) * NDIM * 2;
    const char* pBH = (const char*)g_QH + ((size_t)head * TT + s0) * NDIM * 2;
    const char* pBL = (const char*)g_QL + ((size_t)head * TT + s0) * NDIM * 2;
    const char* srcs[4] = { pAH, pAL, pBH, pBL };

    auto load_stage = [&](int stage, int k0) {
        uint32_t sb = sbase + stage * STAGE_BYTES;
        size_t kb = (size_t)k0 * 2;
        #pragma unroll
        for (int rep = 0; rep < 16; rep++) {
            int idx = tid + rep * 256;
            int tile = idx >> 10, row = (idx >> 3) & 127, c = idx & 7;
            uint32_t dst = sb + tile * TILE_BYTES + row * 128 + ((c ^ (row & 7)) << 4);
            cp_async16(dst, srcs[tile] + (size_t)row * (NDIM * 2) + kb + c * 16);
        }
        CP_COMMIT();
    };

    load_stage(0, 0);
    load_stage(1, KC);

    const int wm = wid >> 1, wn = wid & 1;
    const int m0 = wm * 32, n0 = wn * 64;
    const int rig  = (lane & 7) + ((lane >> 3) & 1) * 8;
    const int csel = lane >> 4;
    const int xr   = lane & 7;

    float acc[2][8][4];
    #pragma unroll
    for (int mt = 0; mt < 2; mt++)
        #pragma unroll
        for (int j = 0; j < 8; j++)
            #pragma unroll
            for (int q = 0; q < 4; q++) acc[mt][j][q] = 0.f;

    const int iters = NDIM / KC;  // 128
    for (int k = 0; k < iters; k++) {
        const int buf = k % NSTAGE;
        if (k + 1 < iters) { CP_WAIT(1); } else { CP_WAIT(0); }
        __syncthreads();                       // single barrier per iter
        if (k + 2 < iters) load_stage((k + 2) % NSTAGE, (k + 2) * KC);

        const uint32_t sb = sbase + buf * STAGE_BYTES;
        const uint32_t aH = sb, aL = sb + TILE_BYTES;
        const uint32_t bH = sb + 2 * TILE_BYTES, bL = sb + 3 * TILE_BYTES;

        #pragma unroll
        for (int kk = 0; kk < 4; kk++) {
            const int c = 2 * kk + csel;
            const uint32_t swz = (uint32_t)((c ^ xr) << 4);

            uint32_t ah[2][4], al[2][4];
            #pragma unroll
            for (int mt = 0; mt < 2; mt++) {
                uint32_t roff = (uint32_t)(m0 + mt * 16 + rig) * 128 + swz;
                ldsm_x4(ah[mt], aH + roff);
                ldsm_x4(al[mt], aL + roff);
            }
            uint32_t bh[4][4], bl[4][4];
            #pragma unroll
            for (int nt = 0; nt < 4; nt++) {
                uint32_t roff = (uint32_t)(n0 + nt * 16 + rig) * 128 + swz;
                ldsm_x4(bh[nt], bH + roff);
                ldsm_x4(bl[nt], bL + roff);
            }
            // Pass 1: hi*hi — 16 MMAs, all distinct accumulators
            #pragma unroll
            for (int mt = 0; mt < 2; mt++)
                #pragma unroll
                for (int nt = 0; nt < 4; nt++) {
                    mma_bf16(acc[mt][2 * nt],     ah[mt], bh[nt][0], bh[nt][2]);
                    mma_bf16(acc[mt][2 * nt + 1], ah[mt], bh[nt][1], bh[nt][3]);
                }
            // Pass 2: hi*lo
            #pragma unroll
            for (int mt = 0; mt < 2; mt++)
                #pragma unroll
                for (int nt = 0; nt < 4; nt++) {
                    mma_bf16(acc[mt][2 * nt],     ah[mt], bl[nt][0], bl[nt][2]);
                    mma_bf16(acc[mt][2 * nt + 1], ah[mt], bl[nt][1], bl[nt][3]);
                }
            // Pass 3: lo*hi
            #pragma unroll
            for (int mt = 0; mt < 2; mt++)
                #pragma unroll
                for (int nt = 0; nt < 4; nt++) {
                    mma_bf16(acc[mt][2 * nt],     al[mt], bh[nt][0], bh[nt][2]);
                    mma_bf16(acc[mt][2 * nt + 1], al[mt], bh[nt][1], bh[nt][3]);
                }
        }
    }

    // Epilogue: tril(-1) * (1 + 0.01*exp(-dt/20)*scale) * rowfac
    // Writes fp32 scores to d_out AND bf16 hi/lo to g_SH/g_SL.
    const float sc = scale_p[0];
    const int lq = lane >> 2, lr = lane & 3;
    __nv_bfloat16* SHh = g_SH + (size_t)head * TT * TT;
    __nv_bfloat16* SLh = g_SL + (size_t)head * TT * TT;
    #pragma unroll
    for (int mt = 0; mt < 2; mt++) {
        const int tr0 = t0 + m0 + mt * 16 + lq;
        const float rf0 = g_rowfac[head * TT + tr0];
        const float rf1 = g_rowfac[head * TT + tr0 + 8];
        #pragma unroll
        for (int j = 0; j < 8; j++) {
            const int scol = s0 + n0 + j * 8 + 2 * lr;
            float2 o0, o1;
            #pragma unroll
            for (int w = 0; w < 2; w++) {
                int s = scol + w;
                float v0 = 0.f, v1 = 0.f;
                if (s < tr0) {
                    float dt = (float)(tr0 - s);
                    v0 = acc[mt][j][w] * (1.0f + 0.01f * __expf(-dt * 0.05f) * sc) * rf0;
                }
                if (s < tr0 + 8) {
                    float dt = (float)(tr0 + 8 - s);
                    v1 = acc[mt][j][2 + w] * (1.0f + 0.01f * __expf(-dt * 0.05f) * sc) * rf1;
                }
                (&o0.x)[w] = v0;
                (&o1.x)[w] = v1;
            }
            *reinterpret_cast<float2*>(&Sh[(size_t)tr0 * TT + scol]) = o0;
            *reinterpret_cast<float2*>(&Sh[(size_t)(tr0 + 8) * TT + scol]) = o1;

            __nv_bfloat16 h0x = __float2bfloat16(o0.x), h0y = __float2bfloat16(o0.y);
            __nv_bfloat16 h1x = __float2bfloat16(o1.x), h1y = __float2bfloat16(o1.y);
            *reinterpret_cast<__nv_bfloat162*>(&SHh[(size_t)tr0 * TT + scol]) =
                __nv_bfloat162(h0x, h0y);
            *reinterpret_cast<__nv_bfloat162*>(&SHh[(size_t)(tr0 + 8) * TT + scol]) =
                __nv_bfloat162(h1x, h1y);
            *reinterpret_cast<__nv_bfloat162*>(&SLh[(size_t)tr0 * TT + scol]) =
                __nv_bfloat162(__float2bfloat16(o0.x - __bfloat162float(h0x)),
                               __float2bfloat16(o0.y - __bfloat162float(h0y)));
            *reinterpret_cast<__nv_bfloat162*>(&SLh[(size_t)(tr0 + 8) * TT + scol]) =
                __nv_bfloat162(__float2bfloat16(o1.x - __bfloat162float(h1x)),
                               __float2bfloat16(o1.y - __bfloat162float(h1y)));
        }
    }
}

// ---------------------------------------------------------------------------
// Kernel 4: output = scores @ V via bf16 split MMA (same 3-pass issue order).
// ---------------------------------------------------------------------------
__global__ __launch_bounds__(256, 1) void out_mma_kernel(float* __restrict__ O) {
    const int jd = blockIdx.x, jt = blockIdx.y, head = blockIdx.z;
    const int b  = head >> 2;
    const int t0 = jt * 128, d0 = jd * 128;
    const int tid = threadIdx.x, wid = tid >> 5, lane = tid & 31;

    extern __shared__ char smem[];
    const uint32_t sbase = smem_u32(smem);

    const char* pAH = (const char*)(g_SH  + (size_t)head * TT * TT + (size_t)t0 * TT);
    const char* pAL = (const char*)(g_SL  + (size_t)head * TT * TT + (size_t)t0 * TT);
    const char* pBH = (const char*)(g_VtH + ((size_t)b * DD + d0) * TT);
    const char* pBL = (const char*)(g_VtL + ((size_t)b * DD + d0) * TT);
    const char* srcs[4] = { pAH, pAL, pBH, pBL };

    auto load_stage = [&](int stage, int k0) {
        uint32_t sb = sbase + stage * STAGE_BYTES;
        size_t kb = (size_t)k0 * 2;
        #pragma unroll
        for (int rep = 0; rep < 16; rep++) {
            int idx = tid + rep * 256;
            int tile = idx >> 10, row = (idx >> 3) & 127, c = idx & 7;
            uint32_t dst = sb + tile * TILE_BYTES + row * 128 + ((c ^ (row & 7)) << 4);
            cp_async16(dst, srcs[tile] + (size_t)row * (TT * 2) + kb + c * 16);
        }
        CP_COMMIT();
    };

    const int iters = 2 * (jt + 1);     // (t0+128)/KC
    load_stage(0, 0);
    if (iters > 1) load_stage(1, KC);

    const int wm = wid >> 1, wn = wid & 1;
    const int m0 = wm * 32, n0 = wn * 64;
    const int rig  = (lane & 7) + ((lane >> 3) & 1) * 8;
    const int csel = lane >> 4;
    const int xr   = lane & 7;

    float acc[2][8][4];
    #pragma unroll
    for (int mt = 0; mt < 2; mt++)
        #pragma unroll
        for (int j = 0; j < 8; j++)
            #pragma unroll
            for (int q = 0; q < 4; q++) acc[mt][j][q] = 0.f;

    for (int k = 0; k < iters; k++) {
        const int buf = k % NSTAGE;
        if (k + 1 < iters) { CP_WAIT(1); } else { CP_WAIT(0); }
        __syncthreads();
        if (k + 2 < iters) load_stage((k + 2) % NSTAGE, (k + 2) * KC);

        const uint32_t sb = sbase + buf * STAGE_BYTES;
        const uint32_t aH = sb, aL = sb + TILE_BYTES;
        const uint32_t bH = sb + 2 * TILE_BYTES, bL = sb + 3 * TILE_BYTES;

        #pragma unroll
        for (int kk = 0; kk < 4; kk++) {
            const int c = 2 * kk + csel;
            const uint32_t swz = (uint32_t)((c ^ xr) << 4);

            uint32_t ah[2][4], al[2][4];
            #pragma unroll
            for (int mt = 0; mt < 2; mt++) {
                uint32_t roff = (uint32_t)(m0 + mt * 16 + rig) * 128 + swz;
                ldsm_x4(ah[mt], aH + roff);
                ldsm_x4(al[mt], aL + roff);
            }
            uint32_t bh[4][4], bl[4][4];
            #pragma unroll
            for (int nt = 0; nt < 4; nt++) {
                uint32_t roff = (uint32_t)(n0 + nt * 16 + rig) * 128 + swz;
                ldsm_x4(bh[nt], bH + roff);
                ldsm_x4(bl[nt], bL + roff);
            }
            #pragma unroll
            for (int mt = 0; mt < 2; mt++)
                #pragma unroll
                for (int nt = 0; nt < 4; nt++) {
                    mma_bf16(acc[mt][2 * nt],     ah[mt], bh[nt][0], bh[nt][2]);
                    mma_bf16(acc[mt][2 * nt + 1], ah[mt], bh[nt][1], bh[nt][3]);
                }
            #pragma unroll
            for (int mt = 0; mt < 2; mt++)
                #pragma unroll
                for (int nt = 0; nt < 4; nt++) {
                    mma_bf16(acc[mt][2 * nt],     ah[mt], bl[nt][0], bl[nt][2]);
                    mma_bf16(acc[mt][2 * nt + 1], ah[mt], bl[nt][1], bl[nt][3]);
                }
            #pragma unroll
            for (int mt = 0; mt < 2; mt++)
                #pragma unroll
                for (int nt = 0; nt < 4; nt++) {
                    mma_bf16(acc[mt][2 * nt],     al[mt], bh[nt][0], bh[nt][2]);
                    mma_bf16(acc[mt][2 * nt + 1], al[mt], bh[nt][1], bh[nt][3]);
                }
        }
    }

    // Epilogue: plain stores to O[head][t][d]
    const int lq = lane >> 2, lr = lane & 3;
    #pragma unroll
    for (int mt = 0; mt < 2; mt++) {
        const int tr0 = t0 + m0 + mt * 16 + lq;
        #pragma unroll
        for (int j = 0; j < 8; j++) {
            const int dcol = d0 + n0 + j * 8 + 2 * lr;
            float2 o0, o1;
            o0.x = acc[mt][j][0]; o0.y = acc[mt][j][1];
            o1.x = acc[mt][j][2]; o1.y = acc[mt][j][3];
            *reinterpret_cast<float2*>(&O[((size_t)head * TT + tr0) * DD + dcol]) = o0;
            *reinterpret_cast<float2*>(&O[((size_t)head * TT + tr0 + 8) * DD + dcol]) = o1;
        }
    }
}

// ---------------------------------------------------------------------------
extern "C" void kernel_launch(void* const* d_in, const int* in_sizes, int n_in,
                              void* d_out, int out_size) {
    const float* Q      = (const float*)d_in[0];
    const float* V      = (const float*)d_in[1];
    const float* traces = (const float*)d_in[2];
    const float* scale  = (const float*)d_in[3];

    float* out    = (float*)d_out;
    float* scores = out + (size_t)NHEAD * TT * DD;

    cudaFuncSetAttribute(scores_mma_kernel,
                         cudaFuncAttributeMaxDynamicSharedMemorySize, SMEM_TOTAL);
    cudaFuncSetAttribute(out_mma_kernel,
                         cudaFuncAttributeMaxDynamicSharedMemorySize, SMEM_TOTAL);

    rope_split_kernel<<<(NHEAD * TT * (NDIM / 2)) / 256, 256>>>(Q);
    gate_kernel<<<NHEAD * TT, 256>>>(traces);
    dim3 gv(DD / 32, TT / 32, 2);
    vsplit_kernel<<<gv, dim3(32, 8)>>>(V);
    dim3 gs(TT / 128, TT / 128, NHEAD);
    scores_mma_kernel<<<gs, 256, SMEM_TOTAL>>>(scale, scores);
    dim3 go(DD / 128, TT / 128, NHEAD);
    out_mma_kernel<<<go, 256, SMEM_TOTAL>>>(out);
}

// round 7
// speedup vs baseline: 3.6714x; 1.2625x over previous
#include <cuda_runtime.h>
#include <cuda_bf16.h>
#include <cuda_fp16.h>
#include <math.h>
#include <stdint.h>

// Problem shape (fixed by the dataset)
#define NHEAD 8        // B*nh = 2*4
#define TT    1024
#define NDIM  8192
#define DD    256

// Static scratch (no allocs allowed)
__device__ __half2       g_QH[(size_t)NHEAD * TT * (NDIM / 2)];   // 128 MB hi part (fp16)
__device__ __half2       g_QL[(size_t)NHEAD * TT * (NDIM / 2)];   // 128 MB lo part (fp16)
__device__ __nv_bfloat16 g_SH[(size_t)NHEAD * TT * TT];           // scores hi (16 MB)
__device__ __nv_bfloat16 g_SL[(size_t)NHEAD * TT * TT];           // scores lo (16 MB)
__device__ __nv_bfloat16 g_VtH[(size_t)2 * DD * TT];              // V^T hi [b][d][s]
__device__ __nv_bfloat16 g_VtL[(size_t)2 * DD * TT];              // V^T lo
__device__ float g_rowfac[NHEAD * TT];

// ---------------------------------------------------------------------------
// PTX helpers (plain sm_80+-class instructions only: cp.async, ldmatrix, mma)
// ---------------------------------------------------------------------------
__device__ __forceinline__ uint32_t smem_u32(const void* p) {
    uint32_t a;
    asm("{ .reg .u64 t; cvta.to.shared.u64 t, %1; cvt.u32.u64 %0, t; }"
        : "=r"(a) : "l"(p));
    return a;
}
__device__ __forceinline__ void cp_async16(uint32_t dst, const void* src) {
    asm volatile("cp.async.cg.shared.global [%0], [%1], 16;" :: "r"(dst), "l"(src) : "memory");
}
#define CP_COMMIT() asm volatile("cp.async.commit_group;" ::: "memory")
#define CP_WAIT(n)  asm volatile("cp.async.wait_group %0;" :: "n"(n) : "memory")

__device__ __forceinline__ void ldsm_x4(uint32_t* r, uint32_t addr) {
    asm volatile("ldmatrix.sync.aligned.m8n8.x4.shared.b16 {%0,%1,%2,%3}, [%4];"
                 : "=r"(r[0]), "=r"(r[1]), "=r"(r[2]), "=r"(r[3]) : "r"(addr));
}
__device__ __forceinline__ void mma_bf16(float* c, const uint32_t* a,
                                         uint32_t b0, uint32_t b1) {
    asm volatile("mma.sync.aligned.m16n8k16.row.col.f32.bf16.bf16.f32 "
                 "{%0,%1,%2,%3}, {%4,%5,%6,%7}, {%8,%9}, {%0,%1,%2,%3};"
                 : "+f"(c[0]), "+f"(c[1]), "+f"(c[2]), "+f"(c[3])
                 : "r"(a[0]), "r"(a[1]), "r"(a[2]), "r"(a[3]), "r"(b0), "r"(b1));
}
__device__ __forceinline__ void mma_fp16(float* c, const uint32_t* a,
                                         uint32_t b0, uint32_t b1) {
    asm volatile("mma.sync.aligned.m16n8k16.row.col.f32.f16.f16.f32 "
                 "{%0,%1,%2,%3}, {%4,%5,%6,%7}, {%8,%9}, {%0,%1,%2,%3};"
                 : "+f"(c[0]), "+f"(c[1]), "+f"(c[2]), "+f"(c[3])
                 : "r"(a[0]), "r"(a[1]), "r"(a[2]), "r"(a[3]), "r"(b0), "r"(b1));
}

#define KC 64
#define TILE_BYTES (128 * 128)          // 128 rows x 128B (64 x 16-bit)

// scores kernel: 3 tiles (AH, AL, BH) per stage, 2 stages -> 96KB, 2 CTAs/SM
#define S_STAGE_BYTES (3 * TILE_BYTES)
#define S_NSTAGE 2
#define S_SMEM (S_NSTAGE * S_STAGE_BYTES)

// out kernel: 4 tiles per stage, 3 stages (unchanged bf16 path)
#define O_STAGE_BYTES (4 * TILE_BYTES)
#define O_NSTAGE 3
#define O_SMEM (O_NSTAGE * O_STAGE_BYTES)

// ---------------------------------------------------------------------------
// Kernel 1: RoPE + hi/lo fp16 split. One thread per even/odd pair.
// ---------------------------------------------------------------------------
__global__ __launch_bounds__(256) void rope_split_kernel(const float* __restrict__ Q) {
    size_t p = (size_t)blockIdx.x * blockDim.x + threadIdx.x;   // pair index
    int    n2  = (int)(p & (NDIM / 2 - 1));
    size_t row = p >> 12;
    int    t   = (int)(row & (TT - 1));

    const float TWO_PI_F = 6.283185307179586f;
    float freq = exp2f(-(float)n2 * (1.0f / 256.0f)) * (1.0f / TWO_PI_F);
    float ph   = fmodf((float)t * freq, 1.0f) * TWO_PI_F;
    float s, c;
    sincosf(ph, &s, &c);

    float2 v = *reinterpret_cast<const float2*>(Q + row * NDIM + 2 * (size_t)n2);
    float ox = v.x * c - v.y * s;
    float oy = v.y * c + v.x * s;

    __half hx = __float2half(ox);
    __half hy = __float2half(oy);
    float lx = ox - __half2float(hx);
    float ly = oy - __half2float(hy);
    g_QH[p] = __half2(hx, hy);
    g_QL[p] = __half2(__float2half(lx), __float2half(ly));
}

// ---------------------------------------------------------------------------
// Kernel 2: trace gate factor = 0.5 + 0.5*sigmoid(mean_D(traces))
// ---------------------------------------------------------------------------
__global__ __launch_bounds__(256) void gate_kernel(const float* __restrict__ traces) {
    int row = blockIdx.x;
    float v = traces[(size_t)row * DD + threadIdx.x];
    #pragma unroll
    for (int o = 16; o; o >>= 1) v += __shfl_down_sync(0xffffffffu, v, o);
    __shared__ float ws[8];
    if ((threadIdx.x & 31) == 0) ws[threadIdx.x >> 5] = v;
    __syncthreads();
    if (threadIdx.x == 0) {
        float s = 0.f;
        #pragma unroll
        for (int i = 0; i < 8; i++) s += ws[i];
        float m = s * (1.0f / 256.0f);
        g_rowfac[row] = 0.5f + 0.5f * (1.0f / (1.0f + expf(-m)));
    }
}

// ---------------------------------------------------------------------------
// Kernel 2b: V transpose + hi/lo split:  Vt[b][d][s] = V[b][s][d]  (bf16)
// ---------------------------------------------------------------------------
__global__ __launch_bounds__(256) void vsplit_kernel(const float* __restrict__ V) {
    const int b = blockIdx.z, d0 = blockIdx.x * 32, s0 = blockIdx.y * 32;
    __shared__ float tile[32][33];
    const int tx = threadIdx.x, ty = threadIdx.y;
    #pragma unroll
    for (int i = 0; i < 4; i++) {
        int s = s0 + ty + 8 * i;
        tile[ty + 8 * i][tx] = V[((size_t)b * TT + s) * DD + d0 + tx];
    }
    __syncthreads();
    #pragma unroll
    for (int i = 0; i < 4; i++) {
        int d = d0 + ty + 8 * i;
        float v = tile[tx][ty + 8 * i];
        __nv_bfloat16 h = __float2bfloat16(v);
        size_t idx = ((size_t)b * DD + d) * TT + s0 + tx;
        g_VtH[idx] = h;
        g_VtL[idx] = __float2bfloat16(v - __bfloat162float(h));
    }
}

// ---------------------------------------------------------------------------
// Kernel 3: scores via fp16 mma.sync, 2-term split (AH*BH + AL*BH).
// CTA 128x128, 8 warps (warp tile 32x64), KC=64, 2-stage pipeline,
// 96KB smem + <=128 regs -> 2 CTAs/SM for latency hiding.
// ---------------------------------------------------------------------------
__global__ __launch_bounds__(256, 2) void scores_mma_kernel(const float* __restrict__ scale_p,
                                                            float* __restrict__ S) {
    const int js = blockIdx.x, jt = blockIdx.y, head = blockIdx.z;
    const int t0 = jt * 128, s0 = js * 128;
    float* Sh = S + (size_t)head * TT * TT;
    const int tid = threadIdx.x, wid = tid >> 5, lane = tid & 31;

    if (js > jt) {   // strictly above diagonal: zero fill fp32 output only
        for (int i = tid; i < 128 * 32; i += 256) {
            int r = i >> 5, c4 = (i & 31) << 2;
            *reinterpret_cast<float4*>(&Sh[(size_t)(t0 + r) * TT + s0 + c4]) =
                make_float4(0.f, 0.f, 0.f, 0.f);
        }
        return;
    }

    extern __shared__ char smem[];
    const uint32_t sbase = smem_u32(smem);

    const char* pAH = (const char*)g_QH + ((size_t)head * TT + t0) * NDIM * 2;
    const char* pAL = (const char*)g_QL + ((size_t)head * TT + t0) * NDIM * 2;
    const char* pBH = (const char*)g_QH + ((size_t)head * TT + s0) * NDIM * 2;
    const char* srcs[3] = { pAH, pAL, pBH };

    // 3 tiles * 1024 chunks / 256 threads = 12 chunks per thread
    auto load_stage = [&](int stage, int k0) {
        uint32_t sb = sbase + stage * S_STAGE_BYTES;
        size_t kb = (size_t)k0 * 2;
        #pragma unroll
        for (int rep = 0; rep < 12; rep++) {
            int idx = tid + rep * 256;
            int tile = idx >> 10, row = (idx >> 3) & 127, c = idx & 7;
            uint32_t dst = sb + tile * TILE_BYTES + row * 128 + ((c ^ (row & 7)) << 4);
            cp_async16(dst, srcs[tile] + (size_t)row * (NDIM * 2) + kb + c * 16);
        }
        CP_COMMIT();
    };

    load_stage(0, 0);

    const int wm = wid >> 1, wn = wid & 1;
    const int m0 = wm * 32, n0 = wn * 64;
    const int rig  = (lane & 7) + ((lane >> 3) & 1) * 8;
    const int csel = lane >> 4;
    const int xr   = lane & 7;

    float acc[2][8][4];
    #pragma unroll
    for (int mt = 0; mt < 2; mt++)
        #pragma unroll
        for (int j = 0; j < 8; j++)
            #pragma unroll
            for (int q = 0; q < 4; q++) acc[mt][j][q] = 0.f;

    const int iters = NDIM / KC;  // 128
    for (int k = 0; k < iters; k++) {
        const int buf = k & 1;
        if (k + 1 < iters) { load_stage((k + 1) & 1, (k + 1) * KC); CP_WAIT(1); }
        else               { CP_WAIT(0); }
        __syncthreads();   // stage k visible to all warps

        const uint32_t sb = sbase + buf * S_STAGE_BYTES;
        const uint32_t aH = sb, aL = sb + TILE_BYTES, bH = sb + 2 * TILE_BYTES;

        #pragma unroll
        for (int kk = 0; kk < 4; kk++) {
            const int c = 2 * kk + csel;
            const uint32_t swz = (uint32_t)((c ^ xr) << 4);

            uint32_t ah[2][4], al[2][4];
            #pragma unroll
            for (int mt = 0; mt < 2; mt++) {
                uint32_t roff = (uint32_t)(m0 + mt * 16 + rig) * 128 + swz;
                ldsm_x4(ah[mt], aH + roff);
                ldsm_x4(al[mt], aL + roff);
            }
            uint32_t bh[4][4];
            #pragma unroll
            for (int nt = 0; nt < 4; nt++) {
                uint32_t roff = (uint32_t)(n0 + nt * 16 + rig) * 128 + swz;
                ldsm_x4(bh[nt], bH + roff);
            }
            // Pass 1: hi*hi
            #pragma unroll
            for (int mt = 0; mt < 2; mt++)
                #pragma unroll
                for (int nt = 0; nt < 4; nt++) {
                    mma_fp16(acc[mt][2 * nt],     ah[mt], bh[nt][0], bh[nt][2]);
                    mma_fp16(acc[mt][2 * nt + 1], ah[mt], bh[nt][1], bh[nt][3]);
                }
            // Pass 2: lo*hi
            #pragma unroll
            for (int mt = 0; mt < 2; mt++)
                #pragma unroll
                for (int nt = 0; nt < 4; nt++) {
                    mma_fp16(acc[mt][2 * nt],     al[mt], bh[nt][0], bh[nt][2]);
                    mma_fp16(acc[mt][2 * nt + 1], al[mt], bh[nt][1], bh[nt][3]);
                }
        }
        __syncthreads();   // compute done before next iter's load overwrites
    }

    // Epilogue: tril(-1) * (1 + 0.01*exp(-dt/20)*scale) * rowfac
    const float sc = scale_p[0];
    const int lq = lane >> 2, lr = lane & 3;
    __nv_bfloat16* SHh = g_SH + (size_t)head * TT * TT;
    __nv_bfloat16* SLh = g_SL + (size_t)head * TT * TT;
    #pragma unroll
    for (int mt = 0; mt < 2; mt++) {
        const int tr0 = t0 + m0 + mt * 16 + lq;
        const float rf0 = g_rowfac[head * TT + tr0];
        const float rf1 = g_rowfac[head * TT + tr0 + 8];
        #pragma unroll
        for (int j = 0; j < 8; j++) {
            const int scol = s0 + n0 + j * 8 + 2 * lr;
            float2 o0, o1;
            #pragma unroll
            for (int w = 0; w < 2; w++) {
                int s = scol + w;
                float v0 = 0.f, v1 = 0.f;
                if (s < tr0) {
                    float dt = (float)(tr0 - s);
                    v0 = acc[mt][j][w] * (1.0f + 0.01f * __expf(-dt * 0.05f) * sc) * rf0;
                }
                if (s < tr0 + 8) {
                    float dt = (float)(tr0 + 8 - s);
                    v1 = acc[mt][j][2 + w] * (1.0f + 0.01f * __expf(-dt * 0.05f) * sc) * rf1;
                }
                (&o0.x)[w] = v0;
                (&o1.x)[w] = v1;
            }
            *reinterpret_cast<float2*>(&Sh[(size_t)tr0 * TT + scol]) = o0;
            *reinterpret_cast<float2*>(&Sh[(size_t)(tr0 + 8) * TT + scol]) = o1;

            __nv_bfloat16 h0x = __float2bfloat16(o0.x), h0y = __float2bfloat16(o0.y);
            __nv_bfloat16 h1x = __float2bfloat16(o1.x), h1y = __float2bfloat16(o1.y);
            *reinterpret_cast<__nv_bfloat162*>(&SHh[(size_t)tr0 * TT + scol]) =
                __nv_bfloat162(h0x, h0y);
            *reinterpret_cast<__nv_bfloat162*>(&SHh[(size_t)(tr0 + 8) * TT + scol]) =
                __nv_bfloat162(h1x, h1y);
            *reinterpret_cast<__nv_bfloat162*>(&SLh[(size_t)tr0 * TT + scol]) =
                __nv_bfloat162(__float2bfloat16(o0.x - __bfloat162float(h0x)),
                               __float2bfloat16(o0.y - __bfloat162float(h0y)));
            *reinterpret_cast<__nv_bfloat162*>(&SLh[(size_t)(tr0 + 8) * TT + scol]) =
                __nv_bfloat162(__float2bfloat16(o1.x - __bfloat162float(h1x)),
                               __float2bfloat16(o1.y - __bfloat162float(h1y)));
        }
    }
}

// ---------------------------------------------------------------------------
// Kernel 4: output = scores @ V via bf16 split MMA (unchanged 3-pass path).
// ---------------------------------------------------------------------------
__global__ __launch_bounds__(256, 1) void out_mma_kernel(float* __restrict__ O) {
    const int jd = blockIdx.x, jt = blockIdx.y, head = blockIdx.z;
    const int b  = head >> 2;
    const int t0 = jt * 128, d0 = jd * 128;
    const int tid = threadIdx.x, wid = tid >> 5, lane = tid & 31;

    extern __shared__ char smem[];
    const uint32_t sbase = smem_u32(smem);

    const char* pAH = (const char*)(g_SH  + (size_t)head * TT * TT + (size_t)t0 * TT);
    const char* pAL = (const char*)(g_SL  + (size_t)head * TT * TT + (size_t)t0 * TT);
    const char* pBH = (const char*)(g_VtH + ((size_t)b * DD + d0) * TT);
    const char* pBL = (const char*)(g_VtL + ((size_t)b * DD + d0) * TT);
    const char* srcs[4] = { pAH, pAL, pBH, pBL };

    auto load_stage = [&](int stage, int k0) {
        uint32_t sb = sbase + stage * O_STAGE_BYTES;
        size_t kb = (size_t)k0 * 2;
        #pragma unroll
        for (int rep = 0; rep < 16; rep++) {
            int idx = tid + rep * 256;
            int tile = idx >> 10, row = (idx >> 3) & 127, c = idx & 7;
            uint32_t dst = sb + tile * TILE_BYTES + row * 128 + ((c ^ (row & 7)) << 4);
            cp_async16(dst, srcs[tile] + (size_t)row * (TT * 2) + kb + c * 16);
        }
        CP_COMMIT();
    };

    const int iters = 2 * (jt + 1);     // (t0+128)/KC
    load_stage(0, 0);
    if (iters > 1) load_stage(1, KC);

    const int wm = wid >> 1, wn = wid & 1;
    const int m0 = wm * 32, n0 = wn * 64;
    const int rig  = (lane & 7) + ((lane >> 3) & 1) * 8;
    const int csel = lane >> 4;
    const int xr   = lane & 7;

    float acc[2][8][4];
    #pragma unroll
    for (int mt = 0; mt < 2; mt++)
        #pragma unroll
        for (int j = 0; j < 8; j++)
            #pragma unroll
            for (int q = 0; q < 4; q++) acc[mt][j][q] = 0.f;

    for (int k = 0; k < iters; k++) {
        const int buf = k % O_NSTAGE;
        if (k + 1 < iters) { CP_WAIT(1); } else { CP_WAIT(0); }
        __syncthreads();
        if (k + 2 < iters) load_stage((k + 2) % O_NSTAGE, (k + 2) * KC);

        const uint32_t sb = sbase + buf * O_STAGE_BYTES;
        const uint32_t aH = sb, aL = sb + TILE_BYTES;
        const uint32_t bH = sb + 2 * TILE_BYTES, bL = sb + 3 * TILE_BYTES;

        #pragma unroll
        for (int kk = 0; kk < 4; kk++) {
            const int c = 2 * kk + csel;
            const uint32_t swz = (uint32_t)((c ^ xr) << 4);

            uint32_t ah[2][4], al[2][4];
            #pragma unroll
            for (int mt = 0; mt < 2; mt++) {
                uint32_t roff = (uint32_t)(m0 + mt * 16 + rig) * 128 + swz;
                ldsm_x4(ah[mt], aH + roff);
                ldsm_x4(al[mt], aL + roff);
            }
            uint32_t bh[4][4], bl[4][4];
            #pragma unroll
            for (int nt = 0; nt < 4; nt++) {
                uint32_t roff = (uint32_t)(n0 + nt * 16 + rig) * 128 + swz;
                ldsm_x4(bh[nt], bH + roff);
                ldsm_x4(bl[nt], bL + roff);
            }
            #pragma unroll
            for (int mt = 0; mt < 2; mt++)
                #pragma unroll
                for (int nt = 0; nt < 4; nt++) {
                    mma_bf16(acc[mt][2 * nt],     ah[mt], bh[nt][0], bh[nt][2]);
                    mma_bf16(acc[mt][2 * nt + 1], ah[mt], bh[nt][1], bh[nt][3]);
                }
            #pragma unroll
            for (int mt = 0; mt < 2; mt++)
                #pragma unroll
                for (int nt = 0; nt < 4; nt++) {
                    mma_bf16(acc[mt][2 * nt],     ah[mt], bl[nt][0], bl[nt][2]);
                    mma_bf16(acc[mt][2 * nt + 1], ah[mt], bl[nt][1], bl[nt][3]);
                }
            #pragma unroll
            for (int mt = 0; mt < 2; mt++)
                #pragma unroll
                for (int nt = 0; nt < 4; nt++) {
                    mma_bf16(acc[mt][2 * nt],     al[mt], bh[nt][0], bh[nt][2]);
                    mma_bf16(acc[mt][2 * nt + 1], al[mt], bh[nt][1], bh[nt][3]);
                }
        }
    }

    const int lq = lane >> 2, lr = lane & 3;
    #pragma unroll
    for (int mt = 0; mt < 2; mt++) {
        const int tr0 = t0 + m0 + mt * 16 + lq;
        #pragma unroll
        for (int j = 0; j < 8; j++) {
            const int dcol = d0 + n0 + j * 8 + 2 * lr;
            float2 o0, o1;
            o0.x = acc[mt][j][0]; o0.y = acc[mt][j][1];
            o1.x = acc[mt][j][2]; o1.y = acc[mt][j][3];
            *reinterpret_cast<float2*>(&O[((size_t)head * TT + tr0) * DD + dcol]) = o0;
            *reinterpret_cast<float2*>(&O[((size_t)head * TT + tr0 + 8) * DD + dcol]) = o1;
        }
    }
}

// ---------------------------------------------------------------------------
extern "C" void kernel_launch(void* const* d_in, const int* in_sizes, int n_in,
                              void* d_out, int out_size) {
    const float* Q      = (const float*)d_in[0];
    const float* V      = (const float*)d_in[1];
    const float* traces = (const float*)d_in[2];
    const float* scale  = (const float*)d_in[3];

    float* out    = (float*)d_out;
    float* scores = out + (size_t)NHEAD * TT * DD;

    cudaFuncSetAttribute(scores_mma_kernel,
                         cudaFuncAttributeMaxDynamicSharedMemorySize, S_SMEM);
    cudaFuncSetAttribute(out_mma_kernel,
                         cudaFuncAttributeMaxDynamicSharedMemorySize, O_SMEM);

    rope_split_kernel<<<(NHEAD * TT * (NDIM / 2)) / 256, 256>>>(Q);
    gate_kernel<<<NHEAD * TT, 256>>>(traces);
    dim3 gv(DD / 32, TT / 32, 2);
    vsplit_kernel<<<gv, dim3(32, 8)>>>(V);
    dim3 gs(TT / 128, TT / 128, NHEAD);
    scores_mma_kernel<<<gs, 256, S_SMEM>>>(scale, scores);
    dim3 go(DD / 128, TT / 128, NHEAD);
    out_mma_kernel<<<go, 256, O_SMEM>>>(out);
}